// round 16
// baseline (speedup 1.0000x reference)
#include <cuda_runtime.h>
#include <cuda_fp16.h>
#include <cstdint>

// Problem constants (fixed by the dataset)
#define N_NODES 12288
#define F_DIMV  512
#define H_DIMV  64
#define E_MAX   393216
#define NTILE   96          // 12288 / 128
#define NUPPER  4656        // 96*97/2 upper-triangular tiles

typedef unsigned long long ull;

// ---------------- f32x2 packed helpers ----------------
__device__ __forceinline__ void ffma2(ull& d, ull a, ull b) {
    asm("fma.rn.f32x2 %0, %1, %2, %0;" : "+l"(d) : "l"(a), "l"(b));
}
__device__ __forceinline__ ull pack2(float x, float y) {
    ull r;
    asm("mov.b64 %0, {%1, %2};" : "=l"(r) : "f"(x), "f"(y));
    return r;
}
__device__ __forceinline__ float2 unpack2(ull v) {
    float2 r;
    asm("mov.b64 {%0, %1}, %2;" : "=f"(r.x), "=f"(r.y) : "l"(v));
    return r;
}

// ---------------- warp MMA helpers (sm_80+ baseline) ----------------
__device__ __forceinline__ uint32_t smem_u32(const void* p) {
    uint32_t a;
    asm("{ .reg .u64 t; cvta.to.shared.u64 t, %1; cvt.u32.u64 %0, t; }"
        : "=r"(a) : "l"(p));
    return a;
}
__device__ __forceinline__ void ldsm_x4(uint32_t& r0, uint32_t& r1, uint32_t& r2,
                                        uint32_t& r3, uint32_t addr) {
    asm volatile("ldmatrix.sync.aligned.m8n8.x4.shared.b16 {%0,%1,%2,%3}, [%4];"
                 : "=r"(r0), "=r"(r1), "=r"(r2), "=r"(r3) : "r"(addr));
}
__device__ __forceinline__ void mma_f16(float d[4], uint32_t a0, uint32_t a1,
                                        uint32_t a2, uint32_t a3,
                                        uint32_t b0, uint32_t b1) {
    asm volatile(
        "mma.sync.aligned.m16n8k16.row.col.f32.f16.f16.f32 "
        "{%0,%1,%2,%3}, {%4,%5,%6,%7}, {%8,%9}, {%0,%1,%2,%3};"
        : "+f"(d[0]), "+f"(d[1]), "+f"(d[2]), "+f"(d[3])
        : "r"(a0), "r"(a1), "r"(a2), "r"(a3), "r"(b0), "r"(b1));
}
__device__ __forceinline__ void stcs4(float* p, float4 v) {
    asm volatile("st.global.cs.v4.f32 [%0], {%1,%2,%3,%4};"
                 :: "l"(p), "f"(v.x), "f"(v.y), "f"(v.z), "f"(v.w) : "memory");
}

// ---------------- scratch (no allocations allowed) ----------------
__device__ float  g_m[N_NODES * H_DIMV];
__device__ float  g_x[N_NODES * H_DIMV];
__device__ float  g_x2[N_NODES * H_DIMV];
__device__ float  g_xa[N_NODES * H_DIMV];
__device__ float  g_aggxa[N_NODES * H_DIMV];
__device__ __half g_sh[N_NODES * H_DIMV];      // structure embedding (fp16)
__device__ int    g_deg[N_NODES];
__device__ int    g_off[N_NODES + 1];
__device__ int    g_cur[N_NODES];
__device__ int    g_csr[E_MAX];

// ---------------- CSR build (int4-vectorized, 4 edges/thread) ----------------
__global__ void k_zero_deg() {
    int i = blockIdx.x * blockDim.x + threadIdx.x;
    if (i * 4 < N_NODES) *(int4*)(&g_deg[i * 4]) = make_int4(0, 0, 0, 0);
}

__global__ void k_count(const int* __restrict__ ei, int E) {
    int i = blockIdx.x * blockDim.x + threadIdx.x;
    int e4 = i * 4;
    if (e4 + 3 < E && !(E & 3)) {
        int4 d = *(const int4*)(ei + E + e4);
        atomicAdd(&g_deg[d.x], 1);
        atomicAdd(&g_deg[d.y], 1);
        atomicAdd(&g_deg[d.z], 1);
        atomicAdd(&g_deg[d.w], 1);
    } else {
        for (int e = e4; e < E && e < e4 + 4; e++)
            atomicAdd(&g_deg[ei[E + e]], 1);
    }
}

// warp-shuffle scan: 1024 threads x 12 items (int4-vectorized), 2 barriers
__global__ void k_scan() {
    __shared__ int wsum[32];
    int t = threadIdx.x;
    int lane = t & 31, w = t >> 5;
    int base = t * 12;
    int d4[12];
#pragma unroll
    for (int i = 0; i < 3; i++) {
        int4 v4 = *(const int4*)(&g_deg[base + 4 * i]);
        d4[4 * i] = v4.x; d4[4 * i + 1] = v4.y;
        d4[4 * i + 2] = v4.z; d4[4 * i + 3] = v4.w;
    }
    int loc[12];
    int s = 0;
#pragma unroll
    for (int i = 0; i < 12; i++) { loc[i] = s; s += d4[i]; }
    int v = s;
#pragma unroll
    for (int d = 1; d < 32; d <<= 1) {
        int u = __shfl_up_sync(0xFFFFFFFFu, v, d);
        if (lane >= d) v += u;
    }
    if (lane == 31) wsum[w] = v;
    __syncthreads();
    if (w == 0) {
        int x = wsum[lane];
#pragma unroll
        for (int d = 1; d < 32; d <<= 1) {
            int u = __shfl_up_sync(0xFFFFFFFFu, x, d);
            if (lane >= d) x += u;
        }
        wsum[lane] = x;
    }
    __syncthreads();
    int prev = v - s + (w ? wsum[w - 1] : 0);
#pragma unroll
    for (int i = 0; i < 3; i++) {
        int4 o4;
        o4.x = prev + loc[4 * i];
        o4.y = prev + loc[4 * i + 1];
        o4.z = prev + loc[4 * i + 2];
        o4.w = prev + loc[4 * i + 3];
        *(int4*)(&g_off[base + 4 * i]) = o4;
        *(int4*)(&g_cur[base + 4 * i]) = o4;
    }
    if (t == 1023) g_off[N_NODES] = wsum[31];
}

__global__ void k_fill(const int* __restrict__ ei, int E) {
    int i = blockIdx.x * blockDim.x + threadIdx.x;
    int e4 = i * 4;
    if (e4 + 3 < E && !(E & 3)) {
        int4 s = *(const int4*)(ei + e4);
        int4 d = *(const int4*)(ei + E + e4);
        g_csr[atomicAdd(&g_cur[d.x], 1)] = s.x;
        g_csr[atomicAdd(&g_cur[d.y], 1)] = s.y;
        g_csr[atomicAdd(&g_cur[d.z], 1)] = s.z;
        g_csr[atomicAdd(&g_cur[d.w], 1)] = s.w;
    } else {
        for (int e = e4; e < E && e < e4 + 4; e++)
            g_csr[atomicAdd(&g_cur[ei[E + e]], 1)] = ei[e];
    }
}

// ---------------- edge aggregation ----------------
__global__ void k_agg(const float* __restrict__ m, const float* __restrict__ bias,
                      float* __restrict__ out, __half* __restrict__ outh, int relu) {
    int w = (blockIdx.x * blockDim.x + threadIdx.x) >> 5;
    if (w >= N_NODES) return;
    int lane = threadIdx.x & 31;
    int e = g_off[w], e1 = g_off[w + 1];
    float ax = 0.f, ay = 0.f;
    for (; e + 1 < e1; e += 2) {
        int sa = g_csr[e], sb = g_csr[e + 1];
        float2 va = *(const float2*)(m + sa * 64 + 2 * lane);
        float2 vb = *(const float2*)(m + sb * 64 + 2 * lane);
        ax += va.x; ay += va.y;
        ax += vb.x; ay += vb.y;
    }
    if (e < e1) {
        float2 va = *(const float2*)(m + g_csr[e] * 64 + 2 * lane);
        ax += va.x; ay += va.y;
    }
    if (bias) { ax += bias[2 * lane]; ay += bias[2 * lane + 1]; }
    if (relu) { ax = fmaxf(ax, 0.f); ay = fmaxf(ay, 0.f); }
    if (outh) {
        ((__half2*)outh)[w * 32 + lane] = __floats2half2_rn(ax, ay);
    } else {
        float2 r; r.x = ax; r.y = ay;
        *(float2*)(out + w * 64 + 2 * lane) = r;
    }
}

// ---------------- GEMM: Y[N,P] = X[N,K] @ W[K,P] (+bias, relu) ----------------
__global__ void __launch_bounds__(256)
k_gemm64(const float* __restrict__ X, const float* __restrict__ W,
         const float* __restrict__ bias, float* __restrict__ Y,
         __half* __restrict__ Yh, int K, int P, int relu) {
    __shared__ __align__(16) float As[32 * 65];
    __shared__ __align__(16) float Bs[32 * 66];
    int tid = threadIdx.x;
    int tx = tid & 15, ty = tid >> 4;
    int rbase = blockIdx.x * 64, cbase = blockIdx.y * 64;

    ull acc[4][2];
#pragma unroll
    for (int i = 0; i < 4; i++)
#pragma unroll
        for (int j = 0; j < 2; j++) acc[i][j] = pack2(0.f, 0.f);

    for (int kc = 0; kc < K; kc += 32) {
        __syncthreads();
#pragma unroll
        for (int i = 0; i < 8; i++) {
            int idx = tid + i * 256;
            int k = idx & 31, row = idx >> 5;
            As[k * 65 + row] = X[(size_t)(rbase + row) * K + kc + k];
        }
#pragma unroll
        for (int i = 0; i < 8; i++) {
            int idx = tid + i * 256;
            int k = idx >> 6, c = idx & 63;
            Bs[k * 66 + c] = W[(size_t)(kc + k) * P + cbase + c];
        }
        __syncthreads();
#pragma unroll 8
        for (int k = 0; k < 32; k++) {
            float a[4]; ull a2[4]; ull b2[2];
#pragma unroll
            for (int i = 0; i < 4; i++) a[i] = As[k * 65 + ty + i * 16];
#pragma unroll
            for (int j = 0; j < 2; j++)
                b2[j] = *(const ull*)(&Bs[k * 66 + 2 * tx + 32 * j]);
#pragma unroll
            for (int i = 0; i < 4; i++) a2[i] = pack2(a[i], a[i]);
#pragma unroll
            for (int i = 0; i < 4; i++)
#pragma unroll
                for (int j = 0; j < 2; j++) ffma2(acc[i][j], a2[i], b2[j]);
        }
    }

#pragma unroll
    for (int i = 0; i < 4; i++) {
        int r = rbase + ty + i * 16;
#pragma unroll
        for (int j = 0; j < 2; j++) {
            int c = cbase + 2 * tx + 32 * j;
            float2 v = unpack2(acc[i][j]);
            if (bias) { v.x += bias[c]; v.y += bias[c + 1]; }
            if (relu) { v.x = fmaxf(v.x, 0.f); v.y = fmaxf(v.y, 0.f); }
            if (Yh) {
                *(__half2*)(&Yh[(size_t)r * P + c]) = __floats2half2_rn(v.x, v.y);
            } else {
                *(float2*)(&Y[(size_t)r * P + c]) = v;
            }
        }
    }
}

// ---------------- C = S @ S^T via single-pass fp16 HMMA ----------------
// R15 changes:
//  * 1-D triangular grid (4656 real CTAs, no no-op blocks)
//  * full-tile [128][132] smem stage (reuses dead operand space): direct tile
//    and mirror tile each stored in ONE round of full 512B-contiguous rows
#define TS   72              // operand row stride in halves (144B)
#define STG  132             // stage row stride (floats)
#define SM_B_OFF 18432
#define SM_SST_TOTAL 67584   // stage 128*132*4 = 67584 >= operands 36864

__global__ void __launch_bounds__(512, 3)
k_sst_mma(const __half* __restrict__ S, float* __restrict__ C) {
    // triangular decode: tile t -> (by, bx), upper triangle row-major
    int t = (int)blockIdx.x;
    int by = (int)((193.0f - sqrtf(193.0f * 193.0f - 8.0f * (float)t)) * 0.5f);
    while ((by + 1) * NTILE - ((by + 1) * by) / 2 <= t) by++;
    while (by * NTILE - (by * (by - 1)) / 2 > t) by--;
    int bx = by + (t - (by * NTILE - (by * (by - 1)) / 2));
    bool diag = (bx == by);

    extern __shared__ __align__(16) char smem[];
    __half* Ah = (__half*)smem;
    __half* Bh = (__half*)(smem + SM_B_OFF);
    float* stg = (float*)smem;                     // [128][STG] after MMA

    int tid = threadIdx.x;
    int wid = tid >> 5;
    int lane = tid & 31;
    const size_t NN = (size_t)N_NODES;

#pragma unroll
    for (int i = 0; i < 2; i++) {
        int idx = tid + i * 512;                   // 0..1023
        int row = idx >> 3, seg = idx & 7;
        const int4* sa = (const int4*)(S + (size_t)(by * 128 + row) * 64) + seg;
        *(int4*)(Ah + row * TS + seg * 8) = *sa;
        if (!diag) {
            const int4* sb = (const int4*)(S + (size_t)(bx * 128 + row) * 64) + seg;
            *(int4*)(Bh + row * TS + seg * 8) = *sb;
        }
    }
    __syncthreads();

    uint32_t aB = smem_u32(Ah);
    uint32_t bB = diag ? aB : smem_u32(Bh);
    int r0 = (wid >> 1) * 16;                      // warp's 16-row group
    int n0 = (wid & 1) * 64;                       // warp's col half

    int lr = lane & 7, ls = lane >> 3;
    uint32_t a_off = (uint32_t)((((ls & 1) * 8 + lr) * TS + (ls >> 1) * 8) * 2);
    uint32_t b_off = (uint32_t)(((lr + (ls >> 1) * 8) * TS + (ls & 1) * 8) * 2);

    float acc[8][4];
#pragma unroll
    for (int nt = 0; nt < 8; nt++)
#pragma unroll
        for (int q = 0; q < 4; q++) acc[nt][q] = 0.f;

#pragma unroll
    for (int ks = 0; ks < 4; ks++) {
        uint32_t koff = (uint32_t)(ks * 32);
        uint32_t a0, a1, a2, a3;
        ldsm_x4(a0, a1, a2, a3, aB + (uint32_t)(r0 * TS * 2) + koff + a_off);
#pragma unroll
        for (int np = 0; np < 4; np++) {
            uint32_t b0, b1, b2, b3;
            ldsm_x4(b0, b1, b2, b3,
                    bB + (uint32_t)((n0 + np * 16) * TS * 2) + koff + b_off);
            mma_f16(acc[2 * np],     a0, a1, a2, a3, b0, b1);
            mma_f16(acc[2 * np + 1], a0, a1, a2, a3, b2, b3);
        }
    }
    __syncthreads();                               // operands dead; stg free

    int gid = lane >> 2, tig = lane & 3;
    int rl = r0 + gid;
    int rbase = by * 128, cbase = bx * 128;

    // ---- direct tile: full-tile deposit, then 512B-contiguous row stores ----
#pragma unroll
    for (int nt = 0; nt < 8; nt++) {
        int cl = n0 + 8 * nt + 2 * tig;
        float2 v0; v0.x = acc[nt][0]; v0.y = acc[nt][1];
        float2 v1; v1.x = acc[nt][2]; v1.y = acc[nt][3];
        *(float2*)&stg[rl * STG + cl] = v0;
        *(float2*)&stg[(rl + 8) * STG + cl] = v1;
    }
    __syncthreads();
#pragma unroll
    for (int i = 0; i < 8; i++) {
        int lin = tid + i * 512;                   // 4096 float4s
        int row = lin >> 5, c4 = (lin & 31) * 4;
        float4 v = *(float4*)&stg[row * STG + c4];
        stcs4(&C[(size_t)(rbase + row) * NN + cbase + c4], v);
    }

    if (diag) return;

    // ---- mirror tile: transposed deposit, then 512B-contiguous row stores ----
    __syncthreads();                               // direct-store reads done
#pragma unroll
    for (int nt = 0; nt < 8; nt++) {
        int cl = n0 + 8 * nt + 2 * tig;
        stg[cl * STG + rl]            = acc[nt][0];
        stg[(cl + 1) * STG + rl]      = acc[nt][1];
        stg[cl * STG + rl + 8]        = acc[nt][2];
        stg[(cl + 1) * STG + rl + 8]  = acc[nt][3];
    }
    __syncthreads();
#pragma unroll
    for (int i = 0; i < 8; i++) {
        int lin = tid + i * 512;
        int row = lin >> 5, c4 = (lin & 31) * 4;
        float4 v = *(float4*)&stg[row * STG + c4];
        stcs4(&C[(size_t)(cbase + row) * NN + rbase + c4], v);
    }
}

// ---------------- launch ----------------
static float* symf(const void* sym) {
    void* p = nullptr;
    cudaGetSymbolAddress(&p, sym);
    return (float*)p;
}

extern "C" void kernel_launch(void* const* d_in, const int* in_sizes, int n_in,
                              void* d_out, int out_size) {
    const float* h   = (const float*)d_in[0];
    const int*   ei  = (const int*)d_in[1];
    const float* W1  = (const float*)d_in[2];
    const float* b1  = (const float*)d_in[3];
    const float* W2  = (const float*)d_in[4];
    const float* b2  = (const float*)d_in[5];
    const float* Wa1 = (const float*)d_in[6];
    const float* ba1 = (const float*)d_in[7];
    const float* Wa2 = (const float*)d_in[8];
    const float* ba2 = (const float*)d_in[9];
    const float* Ws  = (const float*)d_in[10];
    const float* bs  = (const float*)d_in[11];
    float* out = (float*)d_out;
    int E = in_sizes[1] / 2;

    float*  m     = symf(g_m);
    float*  x     = symf(g_x);
    float*  x2    = symf(g_x2);
    float*  xa    = symf(g_xa);
    float*  aggxa = symf(g_aggxa);
    __half* sh    = (__half*)symf(g_sh);

    float* out_xhat = out + (size_t)N_NODES * (size_t)N_NODES;

    int eb4 = (E / 4 + 255) / 256 + 1;

    static cudaStream_t s2 = nullptr;
    static cudaEvent_t ev_fork = nullptr, ev_g512 = nullptr,
                       ev_a2 = nullptr, ev_sst = nullptr;
    if (!s2) {
        cudaFuncSetAttribute(k_sst_mma, cudaFuncAttributeMaxDynamicSharedMemorySize,
                             SM_SST_TOTAL);
        cudaStreamCreateWithFlags(&s2, cudaStreamNonBlocking);
        cudaEventCreateWithFlags(&ev_fork, cudaEventDisableTiming);
        cudaEventCreateWithFlags(&ev_g512, cudaEventDisableTiming);
        cudaEventCreateWithFlags(&ev_a2, cudaEventDisableTiming);
        cudaEventCreateWithFlags(&ev_sst, cudaEventDisableTiming);
    }

    // ---- fork: h@W1 on side stream, CSR build on main stream (independent) ----
    cudaEventRecord(ev_fork, 0);
    cudaStreamWaitEvent(s2, ev_fork, 0);
    k_gemm64<<<dim3(192, 1), 256, 0, s2>>>(h, W1, nullptr, m, nullptr, 512, 64, 0);
    cudaEventRecord(ev_g512, s2);

    k_zero_deg<<<(N_NODES / 4 + 255) / 256, 256>>>();
    k_count<<<eb4, 256>>>(ei, E);
    k_scan<<<1, 1024>>>();
    k_fill<<<eb4, 256>>>(ei, E);

    cudaStreamWaitEvent(0, ev_g512, 0);

    // encoder layer 1: x = relu(agg(h@W1) + b1)
    k_agg<<<1536, 256>>>(m, b1, x, nullptr, 1);
    // encoder layer 2 (agg-then-gemm): x2 = relu(agg(x)@W2 + b2)
    k_agg<<<1536, 256>>>(x, nullptr, m, nullptr, 0);               // A_x -> m
    k_gemm64<<<dim3(192, 1), 256>>>(m, W2, b2, x2, nullptr, 64, 64, 1);
    // shared aggregation for both decoders: A2 = agg(x2) -> m
    k_agg<<<1536, 256>>>(x2, nullptr, m, nullptr, 0);
    cudaEventRecord(ev_a2, 0);

    // ---- side stream: s = relu(A2@Ws + bs) (fp16), then C = s s^T ----
    cudaStreamWaitEvent(s2, ev_a2, 0);
    k_gemm64<<<dim3(192, 1), 256, 0, s2>>>(m, Ws, bs, nullptr, sh, 64, 64, 1);
    k_sst_mma<<<NUPPER, 512, SM_SST_TOTAL, s2>>>(sh, out);
    cudaEventRecord(ev_sst, s2);

    // ---- main stream: attribute decoder ----
    k_gemm64<<<dim3(192, 1), 256>>>(m, Wa1, ba1, xa, nullptr, 64, 64, 1);
    k_agg<<<1536, 256>>>(xa, nullptr, aggxa, nullptr, 0);
    k_gemm64<<<dim3(192, 8), 256>>>(aggxa, Wa2, ba2, out_xhat, nullptr, 64, 512, 1);

    // join
    cudaStreamWaitEvent(0, ev_sst, 0);
}

// round 17
// speedup vs baseline: 1.2857x; 1.2857x over previous
#include <cuda_runtime.h>
#include <cuda_fp16.h>
#include <cstdint>

// Problem constants (fixed by the dataset)
#define N_NODES 12288
#define F_DIMV  512
#define H_DIMV  64
#define E_MAX   393216
#define NTILE   96          // 12288 / 128

typedef unsigned long long ull;

// ---------------- f32x2 packed helpers ----------------
__device__ __forceinline__ void ffma2(ull& d, ull a, ull b) {
    asm("fma.rn.f32x2 %0, %1, %2, %0;" : "+l"(d) : "l"(a), "l"(b));
}
__device__ __forceinline__ ull pack2(float x, float y) {
    ull r;
    asm("mov.b64 %0, {%1, %2};" : "=l"(r) : "f"(x), "f"(y));
    return r;
}
__device__ __forceinline__ float2 unpack2(ull v) {
    float2 r;
    asm("mov.b64 {%0, %1}, %2;" : "=f"(r.x), "=f"(r.y) : "l"(v));
    return r;
}

// ---------------- warp MMA helpers (sm_80+ baseline) ----------------
__device__ __forceinline__ uint32_t smem_u32(const void* p) {
    uint32_t a;
    asm("{ .reg .u64 t; cvta.to.shared.u64 t, %1; cvt.u32.u64 %0, t; }"
        : "=r"(a) : "l"(p));
    return a;
}
__device__ __forceinline__ void ldsm_x4(uint32_t& r0, uint32_t& r1, uint32_t& r2,
                                        uint32_t& r3, uint32_t addr) {
    asm volatile("ldmatrix.sync.aligned.m8n8.x4.shared.b16 {%0,%1,%2,%3}, [%4];"
                 : "=r"(r0), "=r"(r1), "=r"(r2), "=r"(r3) : "r"(addr));
}
__device__ __forceinline__ void mma_f16(float d[4], uint32_t a0, uint32_t a1,
                                        uint32_t a2, uint32_t a3,
                                        uint32_t b0, uint32_t b1) {
    asm volatile(
        "mma.sync.aligned.m16n8k16.row.col.f32.f16.f16.f32 "
        "{%0,%1,%2,%3}, {%4,%5,%6,%7}, {%8,%9}, {%0,%1,%2,%3};"
        : "+f"(d[0]), "+f"(d[1]), "+f"(d[2]), "+f"(d[3])
        : "r"(a0), "r"(a1), "r"(a2), "r"(a3), "r"(b0), "r"(b1));
}
__device__ __forceinline__ void stcs4(float* p, float4 v) {
    asm volatile("st.global.cs.v4.f32 [%0], {%1,%2,%3,%4};"
                 :: "l"(p), "f"(v.x), "f"(v.y), "f"(v.z), "f"(v.w) : "memory");
}

// ---------------- scratch (no allocations allowed) ----------------
__device__ float  g_m[N_NODES * H_DIMV];
__device__ float  g_x[N_NODES * H_DIMV];
__device__ float  g_x2[N_NODES * H_DIMV];
__device__ float  g_xa[N_NODES * H_DIMV];
__device__ float  g_aggxa[N_NODES * H_DIMV];
__device__ __half g_sh[N_NODES * H_DIMV];      // structure embedding (fp16)
__device__ int    g_deg[N_NODES];
__device__ int    g_off[N_NODES + 1];
__device__ int    g_cur[N_NODES];
__device__ int    g_csr[E_MAX];

// ---------------- CSR build (int4-vectorized, 4 edges/thread) ----------------
__global__ void k_zero_deg() {
    int i = blockIdx.x * blockDim.x + threadIdx.x;
    if (i * 4 < N_NODES) *(int4*)(&g_deg[i * 4]) = make_int4(0, 0, 0, 0);
}

__global__ void k_count(const int* __restrict__ ei, int E) {
    int i = blockIdx.x * blockDim.x + threadIdx.x;
    int e4 = i * 4;
    if (e4 + 3 < E && !(E & 3)) {
        int4 d = *(const int4*)(ei + E + e4);
        atomicAdd(&g_deg[d.x], 1);
        atomicAdd(&g_deg[d.y], 1);
        atomicAdd(&g_deg[d.z], 1);
        atomicAdd(&g_deg[d.w], 1);
    } else {
        for (int e = e4; e < E && e < e4 + 4; e++)
            atomicAdd(&g_deg[ei[E + e]], 1);
    }
}

// warp-shuffle scan: 1024 threads x 12 items (int4-vectorized), 2 barriers
__global__ void k_scan() {
    __shared__ int wsum[32];
    int t = threadIdx.x;
    int lane = t & 31, w = t >> 5;
    int base = t * 12;
    int d4[12];
#pragma unroll
    for (int i = 0; i < 3; i++) {
        int4 v4 = *(const int4*)(&g_deg[base + 4 * i]);
        d4[4 * i] = v4.x; d4[4 * i + 1] = v4.y;
        d4[4 * i + 2] = v4.z; d4[4 * i + 3] = v4.w;
    }
    int loc[12];
    int s = 0;
#pragma unroll
    for (int i = 0; i < 12; i++) { loc[i] = s; s += d4[i]; }
    int v = s;
#pragma unroll
    for (int d = 1; d < 32; d <<= 1) {
        int u = __shfl_up_sync(0xFFFFFFFFu, v, d);
        if (lane >= d) v += u;
    }
    if (lane == 31) wsum[w] = v;
    __syncthreads();
    if (w == 0) {
        int x = wsum[lane];
#pragma unroll
        for (int d = 1; d < 32; d <<= 1) {
            int u = __shfl_up_sync(0xFFFFFFFFu, x, d);
            if (lane >= d) x += u;
        }
        wsum[lane] = x;
    }
    __syncthreads();
    int prev = v - s + (w ? wsum[w - 1] : 0);
#pragma unroll
    for (int i = 0; i < 3; i++) {
        int4 o4;
        o4.x = prev + loc[4 * i];
        o4.y = prev + loc[4 * i + 1];
        o4.z = prev + loc[4 * i + 2];
        o4.w = prev + loc[4 * i + 3];
        *(int4*)(&g_off[base + 4 * i]) = o4;
        *(int4*)(&g_cur[base + 4 * i]) = o4;
    }
    if (t == 1023) g_off[N_NODES] = wsum[31];
}

__global__ void k_fill(const int* __restrict__ ei, int E) {
    int i = blockIdx.x * blockDim.x + threadIdx.x;
    int e4 = i * 4;
    if (e4 + 3 < E && !(E & 3)) {
        int4 s = *(const int4*)(ei + e4);
        int4 d = *(const int4*)(ei + E + e4);
        g_csr[atomicAdd(&g_cur[d.x], 1)] = s.x;
        g_csr[atomicAdd(&g_cur[d.y], 1)] = s.y;
        g_csr[atomicAdd(&g_cur[d.z], 1)] = s.z;
        g_csr[atomicAdd(&g_cur[d.w], 1)] = s.w;
    } else {
        for (int e = e4; e < E && e < e4 + 4; e++)
            g_csr[atomicAdd(&g_cur[ei[E + e]], 1)] = ei[e];
    }
}

// ---------------- edge aggregation ----------------
__global__ void k_agg(const float* __restrict__ m, const float* __restrict__ bias,
                      float* __restrict__ out, __half* __restrict__ outh, int relu) {
    int w = (blockIdx.x * blockDim.x + threadIdx.x) >> 5;
    if (w >= N_NODES) return;
    int lane = threadIdx.x & 31;
    int e = g_off[w], e1 = g_off[w + 1];
    float ax = 0.f, ay = 0.f;
    for (; e + 1 < e1; e += 2) {
        int sa = g_csr[e], sb = g_csr[e + 1];
        float2 va = *(const float2*)(m + sa * 64 + 2 * lane);
        float2 vb = *(const float2*)(m + sb * 64 + 2 * lane);
        ax += va.x; ay += va.y;
        ax += vb.x; ay += vb.y;
    }
    if (e < e1) {
        float2 va = *(const float2*)(m + g_csr[e] * 64 + 2 * lane);
        ax += va.x; ay += va.y;
    }
    if (bias) { ax += bias[2 * lane]; ay += bias[2 * lane + 1]; }
    if (relu) { ax = fmaxf(ax, 0.f); ay = fmaxf(ay, 0.f); }
    if (outh) {
        ((__half2*)outh)[w * 32 + lane] = __floats2half2_rn(ax, ay);
    } else {
        float2 r; r.x = ax; r.y = ay;
        *(float2*)(out + w * 64 + 2 * lane) = r;
    }
}

// ---------------- GEMM: Y[N,P] = X[N,K] @ W[K,P] (+bias, relu) ----------------
__global__ void __launch_bounds__(256)
k_gemm64(const float* __restrict__ X, const float* __restrict__ W,
         const float* __restrict__ bias, float* __restrict__ Y,
         __half* __restrict__ Yh, int K, int P, int relu) {
    __shared__ __align__(16) float As[32 * 65];
    __shared__ __align__(16) float Bs[32 * 66];
    int tid = threadIdx.x;
    int tx = tid & 15, ty = tid >> 4;
    int rbase = blockIdx.x * 64, cbase = blockIdx.y * 64;

    ull acc[4][2];
#pragma unroll
    for (int i = 0; i < 4; i++)
#pragma unroll
        for (int j = 0; j < 2; j++) acc[i][j] = pack2(0.f, 0.f);

    for (int kc = 0; kc < K; kc += 32) {
        __syncthreads();
#pragma unroll
        for (int i = 0; i < 8; i++) {
            int idx = tid + i * 256;
            int k = idx & 31, row = idx >> 5;
            As[k * 65 + row] = X[(size_t)(rbase + row) * K + kc + k];
        }
#pragma unroll
        for (int i = 0; i < 8; i++) {
            int idx = tid + i * 256;
            int k = idx >> 6, c = idx & 63;
            Bs[k * 66 + c] = W[(size_t)(kc + k) * P + cbase + c];
        }
        __syncthreads();
#pragma unroll 8
        for (int k = 0; k < 32; k++) {
            float a[4]; ull a2[4]; ull b2[2];
#pragma unroll
            for (int i = 0; i < 4; i++) a[i] = As[k * 65 + ty + i * 16];
#pragma unroll
            for (int j = 0; j < 2; j++)
                b2[j] = *(const ull*)(&Bs[k * 66 + 2 * tx + 32 * j]);
#pragma unroll
            for (int i = 0; i < 4; i++) a2[i] = pack2(a[i], a[i]);
#pragma unroll
            for (int i = 0; i < 4; i++)
#pragma unroll
                for (int j = 0; j < 2; j++) ffma2(acc[i][j], a2[i], b2[j]);
        }
    }

#pragma unroll
    for (int i = 0; i < 4; i++) {
        int r = rbase + ty + i * 16;
#pragma unroll
        for (int j = 0; j < 2; j++) {
            int c = cbase + 2 * tx + 32 * j;
            float2 v = unpack2(acc[i][j]);
            if (bias) { v.x += bias[c]; v.y += bias[c + 1]; }
            if (relu) { v.x = fmaxf(v.x, 0.f); v.y = fmaxf(v.y, 0.f); }
            if (Yh) {
                *(__half2*)(&Yh[(size_t)r * P + c]) = __floats2half2_rn(v.x, v.y);
            } else {
                *(float2*)(&Y[(size_t)r * P + c]) = v;
            }
        }
    }
}

// ---------------- C = S @ S^T via single-pass fp16 HMMA ----------------
// EXACT revert to the R14/R15 305us-winning version (2-D grid, per-half
// stage/store rounds). R16's full-tile restructure regressed 82us — the
// per-half pipeline is at/near the DRAM-write ceiling for this pattern.
#define TS       72          // operand row stride in halves (144B)
#define STG_ROW  68          // row-stage stride (floats)
#define STG_COL  132         // col-stage stride (floats)
#define SM_B_OFF    18432
#define SM_COL_OFF  34816
#define SM_SST_TOTAL 68608

__global__ void __launch_bounds__(512, 3)
k_sst_mma(const __half* __restrict__ S, float* __restrict__ C) {
    int bx = blockIdx.x, by = blockIdx.y;
    if (by > bx) return;
    bool diag = (bx == by);

    extern __shared__ __align__(16) char smem[];
    __half* Ah = (__half*)smem;
    __half* Bh = (__half*)(smem + SM_B_OFF);
    float* srow = (float*)smem;                    // [128][STG_ROW]
    float* scol = (float*)(smem + SM_COL_OFF);     // [64][STG_COL]

    int tid = threadIdx.x;
    int wid = tid >> 5;
    int lane = tid & 31;
    const size_t NN = (size_t)N_NODES;

#pragma unroll
    for (int i = 0; i < 2; i++) {
        int idx = tid + i * 512;                   // 0..1023
        int row = idx >> 3, seg = idx & 7;
        const int4* sa = (const int4*)(S + (size_t)(by * 128 + row) * 64) + seg;
        *(int4*)(Ah + row * TS + seg * 8) = *sa;
        if (!diag) {
            const int4* sb = (const int4*)(S + (size_t)(bx * 128 + row) * 64) + seg;
            *(int4*)(Bh + row * TS + seg * 8) = *sb;
        }
    }
    __syncthreads();

    uint32_t aB = smem_u32(Ah);
    uint32_t bB = diag ? aB : smem_u32(Bh);
    int r0 = (wid >> 1) * 16;
    int n0 = (wid & 1) * 64;

    int lr = lane & 7, ls = lane >> 3;
    uint32_t a_off = (uint32_t)((((ls & 1) * 8 + lr) * TS + (ls >> 1) * 8) * 2);
    uint32_t b_off = (uint32_t)(((lr + (ls >> 1) * 8) * TS + (ls & 1) * 8) * 2);

    float acc[8][4];
#pragma unroll
    for (int nt = 0; nt < 8; nt++)
#pragma unroll
        for (int q = 0; q < 4; q++) acc[nt][q] = 0.f;

#pragma unroll
    for (int ks = 0; ks < 4; ks++) {
        uint32_t koff = (uint32_t)(ks * 32);
        uint32_t a0, a1, a2, a3;
        ldsm_x4(a0, a1, a2, a3, aB + (uint32_t)(r0 * TS * 2) + koff + a_off);
#pragma unroll
        for (int np = 0; np < 4; np++) {
            uint32_t b0, b1, b2, b3;
            ldsm_x4(b0, b1, b2, b3,
                    bB + (uint32_t)((n0 + np * 16) * TS * 2) + koff + b_off);
            mma_f16(acc[2 * np],     a0, a1, a2, a3, b0, b1);
            mma_f16(acc[2 * np + 1], a0, a1, a2, a3, b2, b3);
        }
    }
    __syncthreads();

    int gid = lane >> 2, tig = lane & 3;
    int rbase = by * 128, cbase = bx * 128;

#pragma unroll 1
    for (int h = 0; h < 2; h++) {
        if ((wid & 1) == h) {
            int rl = r0 + gid;
#pragma unroll
            for (int nt = 0; nt < 8; nt++) {
                int cl = 8 * nt + 2 * tig;
                float2 v0; v0.x = acc[nt][0]; v0.y = acc[nt][1];
                float2 v1; v1.x = acc[nt][2]; v1.y = acc[nt][3];
                *(float2*)&srow[rl * STG_ROW + cl] = v0;
                *(float2*)&srow[(rl + 8) * STG_ROW + cl] = v1;
                if (!diag) {
                    scol[cl * STG_COL + rl]            = acc[nt][0];
                    scol[(cl + 1) * STG_COL + rl]      = acc[nt][1];
                    scol[cl * STG_COL + rl + 8]        = acc[nt][2];
                    scol[(cl + 1) * STG_COL + rl + 8]  = acc[nt][3];
                }
            }
        }
        __syncthreads();
#pragma unroll
        for (int i = 0; i < 4; i++) {
            int lin = tid + i * 512;
            int row = lin >> 4, c4 = (lin & 15) * 4;
            float4 v = *(float4*)&srow[row * STG_ROW + c4];
            stcs4(&C[(size_t)(rbase + row) * NN + cbase + h * 64 + c4], v);
        }
        if (!diag) {
#pragma unroll
            for (int i = 0; i < 4; i++) {
                int lin = tid + i * 512;
                int c = lin >> 5, q = (lin & 31) * 4;
                float4 v = *(float4*)&scol[c * STG_COL + q];
                stcs4(&C[(size_t)(cbase + h * 64 + c) * NN + rbase + q], v);
            }
        }
        __syncthreads();
    }
}

// ---------------- launch ----------------
static float* symf(const void* sym) {
    void* p = nullptr;
    cudaGetSymbolAddress(&p, sym);
    return (float*)p;
}

extern "C" void kernel_launch(void* const* d_in, const int* in_sizes, int n_in,
                              void* d_out, int out_size) {
    const float* h   = (const float*)d_in[0];
    const int*   ei  = (const int*)d_in[1];
    const float* W1  = (const float*)d_in[2];
    const float* b1  = (const float*)d_in[3];
    const float* W2  = (const float*)d_in[4];
    const float* b2  = (const float*)d_in[5];
    const float* Wa1 = (const float*)d_in[6];
    const float* ba1 = (const float*)d_in[7];
    const float* Wa2 = (const float*)d_in[8];
    const float* ba2 = (const float*)d_in[9];
    const float* Ws  = (const float*)d_in[10];
    const float* bs  = (const float*)d_in[11];
    float* out = (float*)d_out;
    int E = in_sizes[1] / 2;

    float*  m     = symf(g_m);
    float*  x     = symf(g_x);
    float*  x2    = symf(g_x2);
    float*  xa    = symf(g_xa);
    float*  aggxa = symf(g_aggxa);
    __half* sh    = (__half*)symf(g_sh);

    float* out_xhat = out + (size_t)N_NODES * (size_t)N_NODES;

    int eb4 = (E / 4 + 255) / 256 + 1;

    static cudaStream_t s2 = nullptr;
    static cudaEvent_t ev_fork = nullptr, ev_g512 = nullptr,
                       ev_a2 = nullptr, ev_sst = nullptr;
    if (!s2) {
        cudaFuncSetAttribute(k_sst_mma, cudaFuncAttributeMaxDynamicSharedMemorySize,
                             SM_SST_TOTAL);
        cudaStreamCreateWithFlags(&s2, cudaStreamNonBlocking);
        cudaEventCreateWithFlags(&ev_fork, cudaEventDisableTiming);
        cudaEventCreateWithFlags(&ev_g512, cudaEventDisableTiming);
        cudaEventCreateWithFlags(&ev_a2, cudaEventDisableTiming);
        cudaEventCreateWithFlags(&ev_sst, cudaEventDisableTiming);
    }

    // ---- fork: h@W1 on side stream, CSR build on main stream (independent) ----
    cudaEventRecord(ev_fork, 0);
    cudaStreamWaitEvent(s2, ev_fork, 0);
    k_gemm64<<<dim3(192, 1), 256, 0, s2>>>(h, W1, nullptr, m, nullptr, 512, 64, 0);
    cudaEventRecord(ev_g512, s2);

    k_zero_deg<<<(N_NODES / 4 + 255) / 256, 256>>>();
    k_count<<<eb4, 256>>>(ei, E);
    k_scan<<<1, 1024>>>();
    k_fill<<<eb4, 256>>>(ei, E);

    cudaStreamWaitEvent(0, ev_g512, 0);

    // encoder layer 1: x = relu(agg(h@W1) + b1)
    k_agg<<<1536, 256>>>(m, b1, x, nullptr, 1);
    // encoder layer 2 (agg-then-gemm): x2 = relu(agg(x)@W2 + b2)
    k_agg<<<1536, 256>>>(x, nullptr, m, nullptr, 0);               // A_x -> m
    k_gemm64<<<dim3(192, 1), 256>>>(m, W2, b2, x2, nullptr, 64, 64, 1);
    // shared aggregation for both decoders: A2 = agg(x2) -> m
    k_agg<<<1536, 256>>>(x2, nullptr, m, nullptr, 0);
    cudaEventRecord(ev_a2, 0);

    // ---- side stream: s = relu(A2@Ws + bs) (fp16), then C = s s^T ----
    cudaStreamWaitEvent(s2, ev_a2, 0);
    k_gemm64<<<dim3(192, 1), 256, 0, s2>>>(m, Ws, bs, nullptr, sh, 64, 64, 1);
    k_sst_mma<<<dim3(NTILE, NTILE), 512, SM_SST_TOTAL, s2>>>(sh, out);
    cudaEventRecord(ev_sst, s2);

    // ---- main stream: attribute decoder ----
    k_gemm64<<<dim3(192, 1), 256>>>(m, Wa1, ba1, xa, nullptr, 64, 64, 1);
    k_agg<<<1536, 256>>>(xa, nullptr, aggxa, nullptr, 0);
    k_gemm64<<<dim3(192, 8), 256>>>(aggxa, Wa2, ba2, out_xhat, nullptr, 64, 512, 1);

    // join
    cudaStreamWaitEvent(0, ev_sst, 0);
}